// round 1
// baseline (speedup 1.0000x reference)
#include <cuda_runtime.h>
#include <math.h>

#define B_   8
#define T_   2048
#define DIM_ 512
#define NH_  8
#define NKV_ 4
#define HD_  64
#define KVD_ (NKV_*HD_)
#define BT_  (B_*T_)

// Scratch (device globals: allocation-free per harness rules)
__device__ float g_q[(size_t)BT_*DIM_];
__device__ float g_k[(size_t)BT_*KVD_];
__device__ float g_v[(size_t)BT_*KVD_];
__device__ float g_y[(size_t)BT_*DIM_];

// ---------------------------------------------------------------------------
// C[M,N] = A[M,K] @ W[N,K]^T   (all row-major, M%64==0, N%64==0, K%16==0)
// ---------------------------------------------------------------------------
__global__ __launch_bounds__(256) void gemm_tn(const float* __restrict__ A,
                                               const float* __restrict__ W,
                                               float* __restrict__ C,
                                               int M, int N, int K)
{
    __shared__ float As[16][64];
    __shared__ float Ws[16][64];
    const int tid  = threadIdx.x;
    const int tx   = tid & 15, ty = tid >> 4;
    const int row0 = blockIdx.y << 6, col0 = blockIdx.x << 6;
    const int m    = tid >> 2, kq = (tid & 3) << 2;

    float acc[4][4] = {};

    for (int k0 = 0; k0 < K; k0 += 16) {
        float4 a = *(const float4*)(A + (size_t)(row0 + m) * K + k0 + kq);
        As[kq+0][m] = a.x; As[kq+1][m] = a.y; As[kq+2][m] = a.z; As[kq+3][m] = a.w;
        float4 w = *(const float4*)(W + (size_t)(col0 + m) * K + k0 + kq);
        Ws[kq+0][m] = w.x; Ws[kq+1][m] = w.y; Ws[kq+2][m] = w.z; Ws[kq+3][m] = w.w;
        __syncthreads();
        #pragma unroll
        for (int kk = 0; kk < 16; kk++) {
            float4 ra = *(const float4*)&As[kk][ty << 2];
            float4 rw = *(const float4*)&Ws[kk][tx << 2];
            float rA[4] = {ra.x, ra.y, ra.z, ra.w};
            float rW[4] = {rw.x, rw.y, rw.z, rw.w};
            #pragma unroll
            for (int i = 0; i < 4; i++)
                #pragma unroll
                for (int j = 0; j < 4; j++)
                    acc[i][j] += rA[i] * rW[j];
        }
        __syncthreads();
    }
    #pragma unroll
    for (int i = 0; i < 4; i++) {
        float4 o = make_float4(acc[i][0], acc[i][1], acc[i][2], acc[i][3]);
        *(float4*)(C + (size_t)(row0 + (ty << 2) + i) * N + col0 + (tx << 2)) = o;
    }
}

// ---------------------------------------------------------------------------
// Fused RMSNorm + RoPE, in place. One warp per 64-elem head row.
// Row layout: [B*T, nheads, 64]. t index = (row / nheads) % T.
// ---------------------------------------------------------------------------
__global__ void rms_rope(float* __restrict__ x, int nheads, int totalRows)
{
    int w    = (blockIdx.x * blockDim.x + threadIdx.x) >> 5;
    int lane = threadIdx.x & 31;
    if (w >= totalRows) return;
    int t = (w / nheads) % T_;

    float* row = x + (size_t)w * HD_;
    float x1 = row[lane], x2 = row[lane + 32];
    float ss = x1 * x1 + x2 * x2;
    #pragma unroll
    for (int o = 16; o; o >>= 1) ss += __shfl_xor_sync(0xffffffffu, ss, o);
    float sc = rsqrtf(ss * (1.0f / HD_) + 1.1920928955078125e-07f);
    x1 *= sc; x2 *= sc;

    // inv_freq = 10000^{-(2*lane)/64}; rotate pair (x[lane], x[lane+32])
    double invf = pow(10000.0, -(double)(2 * lane) / (double)HD_);
    float  ang  = (float)((double)t * invf);
    float  s, c;
    sincosf(ang, &s, &c);
    row[lane]      =  x1 * c + x2 * s;
    row[lane + 32] = -x1 * s + x2 * c;
}

// ---------------------------------------------------------------------------
// Causal GQA flash attention, fp32, NO max-subtraction:
// post-RMSNorm ||q||=||k||=8, so |score| = |q.k|/8 <= 8 -> exp(s) <= e^8, safe.
// One q row per thread (q + acc fully in registers). BM=128, BN=64.
// q:[B,T,NH,64]  k,v:[B,T,NKV,64]  y:[B,T,NH,64]
// ---------------------------------------------------------------------------
#define FBM 128
#define FBN 64

__global__ __launch_bounds__(128) void flash(const float* __restrict__ q,
                                             const float* __restrict__ k,
                                             const float* __restrict__ v,
                                             float* __restrict__ y)
{
    __shared__ float k_sh[FBN * HD_];
    __shared__ float v_sh[FBN * HD_];

    const int b   = blockIdx.z, h = blockIdx.y;
    const int m0  = blockIdx.x * FBM;
    const int kvh = h >> 1;            // rep = NH/NKV = 2
    const int tid = threadIdx.x;
    const int qi  = m0 + tid;

    float qreg[HD_];
    const float* qrow = q + ((size_t)(b * T_ + qi) * NH_ + h) * HD_;
    #pragma unroll
    for (int d = 0; d < HD_; d += 4) {
        float4 t4 = *(const float4*)(qrow + d);
        qreg[d]   = t4.x * 0.125f; qreg[d+1] = t4.y * 0.125f;
        qreg[d+2] = t4.z * 0.125f; qreg[d+3] = t4.w * 0.125f;
    }
    float acc[HD_];
    #pragma unroll
    for (int d = 0; d < HD_; d++) acc[d] = 0.f;
    float l = 0.f;

    for (int n0 = 0; n0 < m0 + FBM; n0 += FBN) {
        // cooperative tile load: 8 float4 per thread per tensor
        #pragma unroll
        for (int it = 0; it < (FBN * HD_ / 4) / FBM; it++) {
            int e  = it * FBM + tid;
            int j  = e >> 4;
            int d4 = (e & 15) << 2;
            size_t src = ((size_t)(b * T_ + n0 + j) * NKV_ + kvh) * HD_ + d4;
            *(float4*)(k_sh + j * HD_ + d4) = *(const float4*)(k + src);
            *(float4*)(v_sh + j * HD_ + d4) = *(const float4*)(v + src);
        }
        __syncthreads();

        for (int j = 0; j < FBN; j++) {
            float s = 0.f;
            const float4* kk4 = (const float4*)(k_sh + j * HD_);
            #pragma unroll
            for (int d4 = 0; d4 < 16; d4++) {
                float4 kk = kk4[d4];
                s += qreg[4*d4+0] * kk.x + qreg[4*d4+1] * kk.y
                   + qreg[4*d4+2] * kk.z + qreg[4*d4+3] * kk.w;
            }
            float p = (n0 + j <= qi) ? __expf(s) : 0.f;
            l += p;
            const float4* vv4 = (const float4*)(v_sh + j * HD_);
            #pragma unroll
            for (int d4 = 0; d4 < 16; d4++) {
                float4 vv = vv4[d4];
                acc[4*d4+0] += p * vv.x; acc[4*d4+1] += p * vv.y;
                acc[4*d4+2] += p * vv.z; acc[4*d4+3] += p * vv.w;
            }
        }
        __syncthreads();
    }

    float inv = 1.f / l;
    float* yrow = y + ((size_t)(b * T_ + qi) * NH_ + h) * HD_;
    #pragma unroll
    for (int d = 0; d < HD_; d += 4) {
        float4 o = make_float4(acc[d] * inv, acc[d+1] * inv,
                               acc[d+2] * inv, acc[d+3] * inv);
        *(float4*)(yrow + d) = o;
    }
}

// ---------------------------------------------------------------------------
extern "C" void kernel_launch(void* const* d_in, const int* in_sizes, int n_in,
                              void* d_out, int out_size)
{
    const float* x  = (const float*)d_in[0];
    const float* Wq = (const float*)d_in[1];
    const float* Wk = (const float*)d_in[2];
    const float* Wv = (const float*)d_in[3];
    const float* Wp = (const float*)d_in[4];
    float* out = (float*)d_out;

    float *q, *k, *v, *y;
    cudaGetSymbolAddress((void**)&q, g_q);
    cudaGetSymbolAddress((void**)&k, g_k);
    cudaGetSymbolAddress((void**)&v, g_v);
    cudaGetSymbolAddress((void**)&y, g_y);

    // QKV projections
    gemm_tn<<<dim3(DIM_/64, BT_/64), 256>>>(x, Wq, q, BT_, DIM_, DIM_);
    gemm_tn<<<dim3(KVD_/64, BT_/64), 256>>>(x, Wk, k, BT_, KVD_, DIM_);
    gemm_tn<<<dim3(KVD_/64, BT_/64), 256>>>(x, Wv, v, BT_, KVD_, DIM_);

    // RMSNorm + RoPE on q and k (v untouched)
    rms_rope<<<(BT_*NH_*32)/256,  256>>>(q, NH_,  BT_*NH_);
    rms_rope<<<(BT_*NKV_*32)/256, 256>>>(k, NKV_, BT_*NKV_);

    // Causal GQA flash attention
    flash<<<dim3(T_/FBM, NH_, B_), FBM>>>(q, k, v, y);

    // Output projection
    gemm_tn<<<dim3(DIM_/64, BT_/64), 256>>>(y, Wp, out, BT_, DIM_, DIM_);
}

// round 3
// speedup vs baseline: 1.2019x; 1.2019x over previous
#include <cuda_runtime.h>
#include <cuda_bf16.h>
#include <stdint.h>
#include <math.h>

#define B_   8
#define T_   2048
#define DIM_ 512
#define NH_  8
#define NKV_ 4
#define HD_  64
#define KVD_ (NKV_*HD_)
#define BT_  (B_*T_)

// Scratch (device globals: allocation-free per harness rules)
__device__ float g_q[(size_t)BT_*DIM_];
__device__ float g_k[(size_t)BT_*KVD_];
__device__ float g_v[(size_t)BT_*KVD_];
__device__ float g_y[(size_t)BT_*DIM_];

// ---------------------------------------------------------------------------
// bf16 split-precision tensor-core GEMM:  C[M,N] = A[M,K] @ W[N,K]^T
// A = A_hi + A_lo (bf16 each, joint ~17-bit mantissa).
// C ~= A_hi W_hi + A_hi W_lo + A_lo W_hi   (error ~2^-17 rel)
// Block tile 128x64, BK=16, 8 warps (4 along M x 2 along N), warp tile 32x32.
// ---------------------------------------------------------------------------
#define GBM 128
#define GBN 64
#define GBK 16
#define AST 12   // b32 stride per 16-element row (conflict-free frag loads)

#define MMA_BF16(d, a, b) asm volatile( \
  "mma.sync.aligned.m16n8k16.row.col.f32.bf16.bf16.f32 " \
  "{%0,%1,%2,%3}, {%4,%5,%6,%7}, {%8,%9}, {%0,%1,%2,%3};\n" \
  : "+f"(d[0]), "+f"(d[1]), "+f"(d[2]), "+f"(d[3]) \
  : "r"(a[0]), "r"(a[1]), "r"(a[2]), "r"(a[3]), "r"(b[0]), "r"(b[1]))

__device__ __forceinline__ void split2(float f, unsigned short& h, unsigned short& l)
{
    __nv_bfloat16 hb = __float2bfloat16_rn(f);
    float r = f - __bfloat162float(hb);
    __nv_bfloat16 lb = __float2bfloat16_rn(r);
    h = *(unsigned short*)&hb;
    l = *(unsigned short*)&lb;
}

__device__ __forceinline__ void pack4(float4 f, uint32_t* hi, uint32_t* lo)
{
    unsigned short h0,l0,h1,l1,h2,l2,h3,l3;
    split2(f.x,h0,l0); split2(f.y,h1,l1); split2(f.z,h2,l2); split2(f.w,h3,l3);
    hi[0] = (uint32_t)h0 | ((uint32_t)h1 << 16);
    hi[1] = (uint32_t)h2 | ((uint32_t)h3 << 16);
    lo[0] = (uint32_t)l0 | ((uint32_t)l1 << 16);
    lo[1] = (uint32_t)l2 | ((uint32_t)l3 << 16);
}

__global__ __launch_bounds__(256) void gemm_bf16x2(const float* __restrict__ A,
                                                   const float* __restrict__ W,
                                                   float* __restrict__ C,
                                                   int M, int N, int K)
{
    __shared__ uint32_t As[2][GBM * AST];   // [hi/lo][row*AST + kpair]
    __shared__ uint32_t Bs[2][GBN * AST];

    const int tid  = threadIdx.x;
    const int wid  = tid >> 5, lane = tid & 31;
    const int g    = lane >> 2, tig = lane & 3;
    const int wm   = wid & 3, wn = wid >> 2;
    const int row0 = blockIdx.y * GBM, col0 = blockIdx.x * GBN;

    // gmem load mapping
    const int ar0 = (tid) >> 2,       ak0 = (tid & 3);        // A elem 0
    const int ar1 = (256 + tid) >> 2, ak1 = (tid & 3);        // A elem 1
    const int br  = tid >> 2,         bk  = tid & 3;          // B

    float acc[2][4][4];
    #pragma unroll
    for (int i = 0; i < 2; i++)
        #pragma unroll
        for (int j = 0; j < 4; j++)
            #pragma unroll
            for (int c = 0; c < 4; c++) acc[i][j][c] = 0.f;

    // prologue gmem loads
    float4 pa0 = *(const float4*)(A + (size_t)(row0 + ar0) * K + ak0 * 4);
    float4 pa1 = *(const float4*)(A + (size_t)(row0 + ar1) * K + ak1 * 4);
    float4 pb  = *(const float4*)(W + (size_t)(col0 + br ) * K + bk  * 4);

    for (int k0 = 0; k0 < K; k0 += GBK) {
        // convert + store staged tile
        uint32_t h[2], l[2];
        pack4(pa0, h, l);
        As[0][ar0 * AST + ak0 * 2] = h[0]; As[0][ar0 * AST + ak0 * 2 + 1] = h[1];
        As[1][ar0 * AST + ak0 * 2] = l[0]; As[1][ar0 * AST + ak0 * 2 + 1] = l[1];
        pack4(pa1, h, l);
        As[0][ar1 * AST + ak1 * 2] = h[0]; As[0][ar1 * AST + ak1 * 2 + 1] = h[1];
        As[1][ar1 * AST + ak1 * 2] = l[0]; As[1][ar1 * AST + ak1 * 2 + 1] = l[1];
        pack4(pb, h, l);
        Bs[0][br * AST + bk * 2] = h[0]; Bs[0][br * AST + bk * 2 + 1] = h[1];
        Bs[1][br * AST + bk * 2] = l[0]; Bs[1][br * AST + bk * 2 + 1] = l[1];
        __syncthreads();

        // prefetch next tile (overlaps with MMA below)
        if (k0 + GBK < K) {
            pa0 = *(const float4*)(A + (size_t)(row0 + ar0) * K + k0 + GBK + ak0 * 4);
            pa1 = *(const float4*)(A + (size_t)(row0 + ar1) * K + k0 + GBK + ak1 * 4);
            pb  = *(const float4*)(W + (size_t)(col0 + br ) * K + k0 + GBK + bk  * 4);
        }

        // fragment loads
        uint32_t afh[2][4], afl[2][4], bfh[4][2], bfl[4][2];
        #pragma unroll
        for (int mt = 0; mt < 2; mt++) {
            int rb = (wm * 32 + mt * 16) * AST;
            afh[mt][0] = As[0][rb + g * AST + tig];
            afh[mt][1] = As[0][rb + (g + 8) * AST + tig];
            afh[mt][2] = As[0][rb + g * AST + tig + 4];
            afh[mt][3] = As[0][rb + (g + 8) * AST + tig + 4];
            afl[mt][0] = As[1][rb + g * AST + tig];
            afl[mt][1] = As[1][rb + (g + 8) * AST + tig];
            afl[mt][2] = As[1][rb + g * AST + tig + 4];
            afl[mt][3] = As[1][rb + (g + 8) * AST + tig + 4];
        }
        #pragma unroll
        for (int nt = 0; nt < 4; nt++) {
            int cb = (wn * 32 + nt * 8 + g) * AST;
            bfh[nt][0] = Bs[0][cb + tig];
            bfh[nt][1] = Bs[0][cb + tig + 4];
            bfl[nt][0] = Bs[1][cb + tig];
            bfl[nt][1] = Bs[1][cb + tig + 4];
        }

        #pragma unroll
        for (int mt = 0; mt < 2; mt++)
            #pragma unroll
            for (int nt = 0; nt < 4; nt++) {
                MMA_BF16(acc[mt][nt], afh[mt], bfh[nt]);
                MMA_BF16(acc[mt][nt], afh[mt], bfl[nt]);
                MMA_BF16(acc[mt][nt], afl[mt], bfh[nt]);
            }
        __syncthreads();
    }

    // epilogue: c0,c1 -> (row g, cols 2tig,2tig+1); c2,c3 -> row g+8
    #pragma unroll
    for (int mt = 0; mt < 2; mt++)
        #pragma unroll
        for (int nt = 0; nt < 4; nt++) {
            int row = row0 + wm * 32 + mt * 16 + g;
            int col = col0 + wn * 32 + nt * 8 + 2 * tig;
            *(float2*)(C + (size_t)row * N + col) =
                make_float2(acc[mt][nt][0], acc[mt][nt][1]);
            *(float2*)(C + (size_t)(row + 8) * N + col) =
                make_float2(acc[mt][nt][2], acc[mt][nt][3]);
        }
}

// ---------------------------------------------------------------------------
// Fused RMSNorm + RoPE, in place. One warp per 64-elem head row.
// ---------------------------------------------------------------------------
__global__ void rms_rope(float* __restrict__ x, int nheads, int totalRows)
{
    int w    = (blockIdx.x * blockDim.x + threadIdx.x) >> 5;
    int lane = threadIdx.x & 31;
    if (w >= totalRows) return;
    int t = (w / nheads) % T_;

    float* row = x + (size_t)w * HD_;
    float x1 = row[lane], x2 = row[lane + 32];
    float ss = x1 * x1 + x2 * x2;
    #pragma unroll
    for (int o = 16; o; o >>= 1) ss += __shfl_xor_sync(0xffffffffu, ss, o);
    float sc = rsqrtf(ss * (1.0f / HD_) + 1.1920928955078125e-07f);
    x1 *= sc; x2 *= sc;

    double invf = pow(10000.0, -(double)(2 * lane) / (double)HD_);
    float  ang  = (float)((double)t * invf);
    float  s, c;
    sincosf(ang, &s, &c);
    row[lane]      =  x1 * c + x2 * s;
    row[lane + 32] = -x1 * s + x2 * c;
}

// ---------------------------------------------------------------------------
// Causal GQA flash attention, fp32, no max-subtraction (|score| <= 8).
// ---------------------------------------------------------------------------
#define FBM 128
#define FBN 64

__global__ __launch_bounds__(128) void flash(const float* __restrict__ q,
                                             const float* __restrict__ k,
                                             const float* __restrict__ v,
                                             float* __restrict__ y)
{
    __shared__ float k_sh[FBN * HD_];
    __shared__ float v_sh[FBN * HD_];

    const int b   = blockIdx.z, h = blockIdx.y;
    const int m0  = blockIdx.x * FBM;
    const int kvh = h >> 1;
    const int tid = threadIdx.x;
    const int qi  = m0 + tid;

    float qreg[HD_];
    const float* qrow = q + ((size_t)(b * T_ + qi) * NH_ + h) * HD_;
    #pragma unroll
    for (int d = 0; d < HD_; d += 4) {
        float4 t4 = *(const float4*)(qrow + d);
        qreg[d]   = t4.x * 0.125f; qreg[d+1] = t4.y * 0.125f;
        qreg[d+2] = t4.z * 0.125f; qreg[d+3] = t4.w * 0.125f;
    }
    float acc[HD_];
    #pragma unroll
    for (int d = 0; d < HD_; d++) acc[d] = 0.f;
    float l = 0.f;

    for (int n0 = 0; n0 < m0 + FBM; n0 += FBN) {
        #pragma unroll
        for (int it = 0; it < (FBN * HD_ / 4) / FBM; it++) {
            int e  = it * FBM + tid;
            int j  = e >> 4;
            int d4 = (e & 15) << 2;
            size_t src = ((size_t)(b * T_ + n0 + j) * NKV_ + kvh) * HD_ + d4;
            *(float4*)(k_sh + j * HD_ + d4) = *(const float4*)(k + src);
            *(float4*)(v_sh + j * HD_ + d4) = *(const float4*)(v + src);
        }
        __syncthreads();

        for (int j = 0; j < FBN; j++) {
            float s = 0.f;
            const float4* kk4 = (const float4*)(k_sh + j * HD_);
            #pragma unroll
            for (int d4 = 0; d4 < 16; d4++) {
                float4 kk = kk4[d4];
                s += qreg[4*d4+0] * kk.x + qreg[4*d4+1] * kk.y
                   + qreg[4*d4+2] * kk.z + qreg[4*d4+3] * kk.w;
            }
            float p = (n0 + j <= qi) ? __expf(s) : 0.f;
            l += p;
            const float4* vv4 = (const float4*)(v_sh + j * HD_);
            #pragma unroll
            for (int d4 = 0; d4 < 16; d4++) {
                float4 vv = vv4[d4];
                acc[4*d4+0] += p * vv.x; acc[4*d4+1] += p * vv.y;
                acc[4*d4+2] += p * vv.z; acc[4*d4+3] += p * vv.w;
            }
        }
        __syncthreads();
    }

    float inv = 1.f / l;
    float* yrow = y + ((size_t)(b * T_ + qi) * NH_ + h) * HD_;
    #pragma unroll
    for (int d = 0; d < HD_; d += 4) {
        float4 o = make_float4(acc[d] * inv, acc[d+1] * inv,
                               acc[d+2] * inv, acc[d+3] * inv);
        *(float4*)(yrow + d) = o;
    }
}

// ---------------------------------------------------------------------------
extern "C" void kernel_launch(void* const* d_in, const int* in_sizes, int n_in,
                              void* d_out, int out_size)
{
    const float* x  = (const float*)d_in[0];
    const float* Wq = (const float*)d_in[1];
    const float* Wk = (const float*)d_in[2];
    const float* Wv = (const float*)d_in[3];
    const float* Wp = (const float*)d_in[4];
    float* out = (float*)d_out;

    float *q, *k, *v, *y;
    cudaGetSymbolAddress((void**)&q, g_q);
    cudaGetSymbolAddress((void**)&k, g_k);
    cudaGetSymbolAddress((void**)&v, g_v);
    cudaGetSymbolAddress((void**)&y, g_y);

    // QKV projections (tensor-core bf16 split)
    gemm_bf16x2<<<dim3(DIM_/GBN, BT_/GBM), 256>>>(x, Wq, q, BT_, DIM_, DIM_);
    gemm_bf16x2<<<dim3(KVD_/GBN, BT_/GBM), 256>>>(x, Wk, k, BT_, KVD_, DIM_);
    gemm_bf16x2<<<dim3(KVD_/GBN, BT_/GBM), 256>>>(x, Wv, v, BT_, KVD_, DIM_);

    // RMSNorm + RoPE on q and k
    rms_rope<<<(BT_*NH_*32)/256,  256>>>(q, NH_,  BT_*NH_);
    rms_rope<<<(BT_*NKV_*32)/256, 256>>>(k, NKV_, BT_*NKV_);

    // Causal GQA flash attention
    flash<<<dim3(T_/FBM, NH_, B_), FBM>>>(q, k, v, y);

    // Output projection
    gemm_bf16x2<<<dim3(DIM_/GBN, BT_/GBM), 256>>>(y, Wp, out, BT_, DIM_, DIM_);
}

// round 4
// speedup vs baseline: 3.6848x; 3.0657x over previous
#include <cuda_runtime.h>
#include <cuda_bf16.h>
#include <stdint.h>
#include <math.h>

#define B_   8
#define T_   2048
#define DIM_ 512
#define NH_  8
#define NKV_ 4
#define HD_  64
#define KVD_ (NKV_*HD_)
#define BT_  (B_*T_)

// fp32 scratch
__device__ float g_q[(size_t)BT_*DIM_];
__device__ float g_k[(size_t)BT_*KVD_];
__device__ float g_v[(size_t)BT_*KVD_];
__device__ float g_y[(size_t)BT_*DIM_];
// bf16 split scratch (hi/lo)
__device__ uint16_t g_qh[(size_t)BT_*DIM_], g_ql[(size_t)BT_*DIM_];
__device__ uint16_t g_kh[(size_t)BT_*KVD_], g_kl[(size_t)BT_*KVD_];
__device__ uint16_t g_vh[(size_t)BT_*KVD_], g_vl[(size_t)BT_*KVD_];

#define MMA_BF16(d, a, b) asm volatile( \
  "mma.sync.aligned.m16n8k16.row.col.f32.bf16.bf16.f32 " \
  "{%0,%1,%2,%3}, {%4,%5,%6,%7}, {%8,%9}, {%0,%1,%2,%3};\n" \
  : "+f"(d[0]), "+f"(d[1]), "+f"(d[2]), "+f"(d[3]) \
  : "r"(a[0]), "r"(a[1]), "r"(a[2]), "r"(a[3]), "r"(b[0]), "r"(b[1]))

#define LDMX2T(r0, r1, a) asm volatile( \
  "ldmatrix.sync.aligned.m8n8.x2.trans.shared.b16 {%0,%1}, [%2];" \
  : "=r"(r0), "=r"(r1) : "r"(a))

__device__ __forceinline__ void split2(float f, uint16_t& h, uint16_t& l)
{
    __nv_bfloat16 hb = __float2bfloat16_rn(f);
    float r = f - __bfloat162float(hb);
    __nv_bfloat16 lb = __float2bfloat16_rn(r);
    h = *(uint16_t*)&hb;
    l = *(uint16_t*)&lb;
}

__device__ __forceinline__ void pack4(float4 f, uint32_t* hi, uint32_t* lo)
{
    uint16_t h0,l0,h1,l1,h2,l2,h3,l3;
    split2(f.x,h0,l0); split2(f.y,h1,l1); split2(f.z,h2,l2); split2(f.w,h3,l3);
    hi[0] = (uint32_t)h0 | ((uint32_t)h1 << 16);
    hi[1] = (uint32_t)h2 | ((uint32_t)h3 << 16);
    lo[0] = (uint32_t)l0 | ((uint32_t)l1 << 16);
    lo[1] = (uint32_t)l2 | ((uint32_t)l3 << 16);
}

// ---------------------------------------------------------------------------
// bf16 split-precision tensor-core GEMM:  C[M,N] = A[M,K] @ W[N,K]^T
// ---------------------------------------------------------------------------
#define GBM 128
#define GBN 64
#define GBK 16
#define AST 12

__global__ __launch_bounds__(256) void gemm_bf16x2(const float* __restrict__ A,
                                                   const float* __restrict__ W,
                                                   float* __restrict__ C,
                                                   int M, int N, int K)
{
    __shared__ uint32_t As[2][GBM * AST];
    __shared__ uint32_t Bs[2][GBN * AST];

    const int tid  = threadIdx.x;
    const int wid  = tid >> 5, lane = tid & 31;
    const int g    = lane >> 2, tig = lane & 3;
    const int wm   = wid & 3, wn = wid >> 2;
    const int row0 = blockIdx.y * GBM, col0 = blockIdx.x * GBN;

    const int ar0 = (tid) >> 2,       ak0 = (tid & 3);
    const int ar1 = (256 + tid) >> 2, ak1 = (tid & 3);
    const int br  = tid >> 2,         bk  = tid & 3;

    float acc[2][4][4];
    #pragma unroll
    for (int i = 0; i < 2; i++)
        #pragma unroll
        for (int j = 0; j < 4; j++)
            #pragma unroll
            for (int c = 0; c < 4; c++) acc[i][j][c] = 0.f;

    float4 pa0 = *(const float4*)(A + (size_t)(row0 + ar0) * K + ak0 * 4);
    float4 pa1 = *(const float4*)(A + (size_t)(row0 + ar1) * K + ak1 * 4);
    float4 pb  = *(const float4*)(W + (size_t)(col0 + br ) * K + bk  * 4);

    for (int k0 = 0; k0 < K; k0 += GBK) {
        uint32_t h[2], l[2];
        pack4(pa0, h, l);
        As[0][ar0 * AST + ak0 * 2] = h[0]; As[0][ar0 * AST + ak0 * 2 + 1] = h[1];
        As[1][ar0 * AST + ak0 * 2] = l[0]; As[1][ar0 * AST + ak0 * 2 + 1] = l[1];
        pack4(pa1, h, l);
        As[0][ar1 * AST + ak1 * 2] = h[0]; As[0][ar1 * AST + ak1 * 2 + 1] = h[1];
        As[1][ar1 * AST + ak1 * 2] = l[0]; As[1][ar1 * AST + ak1 * 2 + 1] = l[1];
        pack4(pb, h, l);
        Bs[0][br * AST + bk * 2] = h[0]; Bs[0][br * AST + bk * 2 + 1] = h[1];
        Bs[1][br * AST + bk * 2] = l[0]; Bs[1][br * AST + bk * 2 + 1] = l[1];
        __syncthreads();

        if (k0 + GBK < K) {
            pa0 = *(const float4*)(A + (size_t)(row0 + ar0) * K + k0 + GBK + ak0 * 4);
            pa1 = *(const float4*)(A + (size_t)(row0 + ar1) * K + k0 + GBK + ak1 * 4);
            pb  = *(const float4*)(W + (size_t)(col0 + br ) * K + k0 + GBK + bk  * 4);
        }

        uint32_t afh[2][4], afl[2][4], bfh[4][2], bfl[4][2];
        #pragma unroll
        for (int mt = 0; mt < 2; mt++) {
            int rb = (wm * 32 + mt * 16) * AST;
            afh[mt][0] = As[0][rb + g * AST + tig];
            afh[mt][1] = As[0][rb + (g + 8) * AST + tig];
            afh[mt][2] = As[0][rb + g * AST + tig + 4];
            afh[mt][3] = As[0][rb + (g + 8) * AST + tig + 4];
            afl[mt][0] = As[1][rb + g * AST + tig];
            afl[mt][1] = As[1][rb + (g + 8) * AST + tig];
            afl[mt][2] = As[1][rb + g * AST + tig + 4];
            afl[mt][3] = As[1][rb + (g + 8) * AST + tig + 4];
        }
        #pragma unroll
        for (int nt = 0; nt < 4; nt++) {
            int cb = (wn * 32 + nt * 8 + g) * AST;
            bfh[nt][0] = Bs[0][cb + tig];
            bfh[nt][1] = Bs[0][cb + tig + 4];
            bfl[nt][0] = Bs[1][cb + tig];
            bfl[nt][1] = Bs[1][cb + tig + 4];
        }

        #pragma unroll
        for (int mt = 0; mt < 2; mt++)
            #pragma unroll
            for (int nt = 0; nt < 4; nt++) {
                MMA_BF16(acc[mt][nt], afh[mt], bfh[nt]);
                MMA_BF16(acc[mt][nt], afh[mt], bfl[nt]);
                MMA_BF16(acc[mt][nt], afl[mt], bfh[nt]);
            }
        __syncthreads();
    }

    #pragma unroll
    for (int mt = 0; mt < 2; mt++)
        #pragma unroll
        for (int nt = 0; nt < 4; nt++) {
            int row = row0 + wm * 32 + mt * 16 + g;
            int col = col0 + wn * 32 + nt * 8 + 2 * tig;
            *(float2*)(C + (size_t)row * N + col) =
                make_float2(acc[mt][nt][0], acc[mt][nt][1]);
            *(float2*)(C + (size_t)(row + 8) * N + col) =
                make_float2(acc[mt][nt][2], acc[mt][nt][3]);
        }
}

// ---------------------------------------------------------------------------
// Fused RMSNorm + RoPE + scale + bf16 split. One warp per 64-elem head row.
// Emits hi/lo bf16 only (flash consumes bf16 directly).
// ---------------------------------------------------------------------------
__global__ void rms_rope_split(const float* __restrict__ x,
                               uint16_t* __restrict__ xh,
                               uint16_t* __restrict__ xl,
                               int nheads, int totalRows, float scale)
{
    int w    = (blockIdx.x * blockDim.x + threadIdx.x) >> 5;
    int lane = threadIdx.x & 31;
    if (w >= totalRows) return;
    int t = (w / nheads) % T_;

    const float* row = x + (size_t)w * HD_;
    float x1 = row[lane], x2 = row[lane + 32];
    float ss = x1 * x1 + x2 * x2;
    #pragma unroll
    for (int o = 16; o; o >>= 1) ss += __shfl_xor_sync(0xffffffffu, ss, o);
    float sc = rsqrtf(ss * (1.0f / HD_) + 1.1920928955078125e-07f);
    x1 *= sc; x2 *= sc;

    double invf = pow(10000.0, -(double)(2 * lane) / (double)HD_);
    float  ang  = (float)((double)t * invf);
    float  s, c;
    sincosf(ang, &s, &c);
    float o1 = ( x1 * c + x2 * s) * scale;
    float o2 = (-x1 * s + x2 * c) * scale;

    uint16_t h, l;
    split2(o1, h, l);
    xh[(size_t)w * HD_ + lane] = h;      xl[(size_t)w * HD_ + lane] = l;
    split2(o2, h, l);
    xh[(size_t)w * HD_ + lane + 32] = h; xl[(size_t)w * HD_ + lane + 32] = l;
}

// v -> hi/lo bf16 (vectorized)
__global__ void split_v(const float* __restrict__ v,
                        uint16_t* __restrict__ vh, uint16_t* __restrict__ vl, int n4)
{
    int i = blockIdx.x * blockDim.x + threadIdx.x;
    if (i >= n4) return;
    float4 f = ((const float4*)v)[i];
    uint32_t hi[2], lo[2];
    pack4(f, hi, lo);
    ((uint2*)vh)[i] = make_uint2(hi[0], hi[1]);
    ((uint2*)vl)[i] = make_uint2(lo[0], lo[1]);
}

// ---------------------------------------------------------------------------
// Tensor-core causal GQA flash attention, split-bf16, no max-subtraction.
// BM=64 rows/block, 4 warps x 16 rows. BN=64 KV tile.
// smem row stride 36 words -> conflict-free frag LDS + ldmatrix.
// ---------------------------------------------------------------------------
__global__ __launch_bounds__(128) void flash_tc(
    const uint16_t* __restrict__ qh, const uint16_t* __restrict__ ql,
    const uint16_t* __restrict__ kh, const uint16_t* __restrict__ kl,
    const uint16_t* __restrict__ vh, const uint16_t* __restrict__ vl,
    float* __restrict__ y)
{
    __shared__ uint32_t Kh_s[64*36], Kl_s[64*36], Vh_s[64*36], Vl_s[64*36];

    const int b = blockIdx.z, h = blockIdx.y;
    const int m0 = blockIdx.x * 64;
    const int kvh = h >> 1;
    const int tid = threadIdx.x, wid = tid >> 5, lane = tid & 31;
    const int g = lane >> 2, tig = lane & 3;
    const int row0 = m0 + wid * 16;

    const uint32_t* qh32 = (const uint32_t*)qh;
    const uint32_t* ql32 = (const uint32_t*)ql;
    const uint32_t* kh32 = (const uint32_t*)kh;
    const uint32_t* kl32 = (const uint32_t*)kl;
    const uint32_t* vh32 = (const uint32_t*)vh;
    const uint32_t* vl32 = (const uint32_t*)vl;

    // persistent Q a-fragments (hi/lo)
    uint32_t qfh[4][4], qfl[4][4];
    {
        size_t q0 = ((size_t)(b * T_ + row0 + g) * NH_ + h) * 32;
        size_t q1 = ((size_t)(b * T_ + row0 + g + 8) * NH_ + h) * 32;
        #pragma unroll
        for (int kk = 0; kk < 4; kk++) {
            qfh[kk][0] = qh32[q0 + kk*8 + tig];
            qfh[kk][1] = qh32[q1 + kk*8 + tig];
            qfh[kk][2] = qh32[q0 + kk*8 + 4 + tig];
            qfh[kk][3] = qh32[q1 + kk*8 + 4 + tig];
            qfl[kk][0] = ql32[q0 + kk*8 + tig];
            qfl[kk][1] = ql32[q1 + kk*8 + tig];
            qfl[kk][2] = ql32[q0 + kk*8 + 4 + tig];
            qfl[kk][3] = ql32[q1 + kk*8 + 4 + tig];
        }
    }

    float o[8][4];
    #pragma unroll
    for (int nt = 0; nt < 8; nt++)
        #pragma unroll
        for (int c = 0; c < 4; c++) o[nt][c] = 0.f;
    float lsum0 = 0.f, lsum1 = 0.f;

    uint32_t vh_base = (uint32_t)__cvta_generic_to_shared(Vh_s);
    uint32_t vl_base = (uint32_t)__cvta_generic_to_shared(Vl_s);

    for (int n0 = 0; n0 <= m0; n0 += 64) {
        // cooperative tile load (bf16 words, no conversion)
        #pragma unroll
        for (int it = 0; it < 4; it++) {
            int e = it * 128 + tid;
            int j = e >> 3, dq = (e & 7) * 4;
            size_t src = ((size_t)(b * T_ + n0 + j) * NKV_ + kvh) * 32 + dq;
            int dst = j * 36 + dq;
            *(uint4*)&Kh_s[dst] = *(const uint4*)&kh32[src];
            *(uint4*)&Kl_s[dst] = *(const uint4*)&kl32[src];
            *(uint4*)&Vh_s[dst] = *(const uint4*)&vh32[src];
            *(uint4*)&Vl_s[dst] = *(const uint4*)&vl32[src];
        }
        __syncthreads();

        // S = Q K^T (3-way split)
        float sfr[8][4];
        #pragma unroll
        for (int nt = 0; nt < 8; nt++) {
            #pragma unroll
            for (int c = 0; c < 4; c++) sfr[nt][c] = 0.f;
            #pragma unroll
            for (int kk = 0; kk < 4; kk++) {
                uint32_t bh[2], bl[2];
                int bw = (nt*8 + g)*36 + kk*8 + tig;
                bh[0] = Kh_s[bw]; bh[1] = Kh_s[bw + 4];
                bl[0] = Kl_s[bw]; bl[1] = Kl_s[bw + 4];
                MMA_BF16(sfr[nt], qfh[kk], bh);
                MMA_BF16(sfr[nt], qfh[kk], bl);
                MMA_BF16(sfr[nt], qfl[kk], bh);
            }
        }

        // mask + exp + rowsum, pack P into a-frags (registers only)
        uint32_t pfh[4][4], pfl[4][4];
        const bool diag = (n0 == m0);
        #pragma unroll
        for (int nt = 0; nt < 8; nt++) {
            float p0 = __expf(sfr[nt][0]);
            float p1 = __expf(sfr[nt][1]);
            float p2 = __expf(sfr[nt][2]);
            float p3 = __expf(sfr[nt][3]);
            if (diag) {
                int col = n0 + nt*8 + 2*tig;
                int r0 = row0 + g, r1 = row0 + g + 8;
                if (col     > r0) p0 = 0.f;
                if (col + 1 > r0) p1 = 0.f;
                if (col     > r1) p2 = 0.f;
                if (col + 1 > r1) p3 = 0.f;
            }
            lsum0 += p0 + p1;
            lsum1 += p2 + p3;
            uint16_t h0,l0,h1,l1,h2,l2,h3,l3;
            split2(p0,h0,l0); split2(p1,h1,l1); split2(p2,h2,l2); split2(p3,h3,l3);
            int kk = nt >> 1, s = (nt & 1) * 2;
            pfh[kk][s]   = (uint32_t)h0 | ((uint32_t)h1 << 16);
            pfh[kk][s+1] = (uint32_t)h2 | ((uint32_t)h3 << 16);
            pfl[kk][s]   = (uint32_t)l0 | ((uint32_t)l1 << 16);
            pfl[kk][s+1] = (uint32_t)l2 | ((uint32_t)l3 << 16);
        }

        // O += P V  (V b-frags via ldmatrix.trans)
        #pragma unroll
        for (int nt = 0; nt < 8; nt++) {
            #pragma unroll
            for (int kk = 0; kk < 4; kk++) {
                uint32_t off = ((16*kk + (lane & 15)) * 36 + nt*4) * 4;
                uint32_t bh[2], bl[2];
                LDMX2T(bh[0], bh[1], vh_base + off);
                LDMX2T(bl[0], bl[1], vl_base + off);
                MMA_BF16(o[nt], pfh[kk], bh);
                MMA_BF16(o[nt], pfh[kk], bl);
                MMA_BF16(o[nt], pfl[kk], bh);
            }
        }
        __syncthreads();
    }

    // rowsum reduce across the 4 lanes of each row group
    lsum0 += __shfl_xor_sync(0xffffffffu, lsum0, 1);
    lsum0 += __shfl_xor_sync(0xffffffffu, lsum0, 2);
    lsum1 += __shfl_xor_sync(0xffffffffu, lsum1, 1);
    lsum1 += __shfl_xor_sync(0xffffffffu, lsum1, 2);
    float i0 = 1.f / lsum0, i1 = 1.f / lsum1;

    float* y0 = y + ((size_t)(b * T_ + row0 + g) * NH_ + h) * HD_;
    float* y1 = y + ((size_t)(b * T_ + row0 + g + 8) * NH_ + h) * HD_;
    #pragma unroll
    for (int nt = 0; nt < 8; nt++) {
        int col = nt*8 + 2*tig;
        *(float2*)(y0 + col) = make_float2(o[nt][0] * i0, o[nt][1] * i0);
        *(float2*)(y1 + col) = make_float2(o[nt][2] * i1, o[nt][3] * i1);
    }
}

// ---------------------------------------------------------------------------
extern "C" void kernel_launch(void* const* d_in, const int* in_sizes, int n_in,
                              void* d_out, int out_size)
{
    const float* x  = (const float*)d_in[0];
    const float* Wq = (const float*)d_in[1];
    const float* Wk = (const float*)d_in[2];
    const float* Wv = (const float*)d_in[3];
    const float* Wp = (const float*)d_in[4];
    float* out = (float*)d_out;

    float *q, *k, *v, *y;
    cudaGetSymbolAddress((void**)&q, g_q);
    cudaGetSymbolAddress((void**)&k, g_k);
    cudaGetSymbolAddress((void**)&v, g_v);
    cudaGetSymbolAddress((void**)&y, g_y);
    uint16_t *qhp, *qlp, *khp, *klp, *vhp, *vlp;
    cudaGetSymbolAddress((void**)&qhp, g_qh);
    cudaGetSymbolAddress((void**)&qlp, g_ql);
    cudaGetSymbolAddress((void**)&khp, g_kh);
    cudaGetSymbolAddress((void**)&klp, g_kl);
    cudaGetSymbolAddress((void**)&vhp, g_vh);
    cudaGetSymbolAddress((void**)&vlp, g_vl);

    // QKV projections (tensor-core bf16 split)
    gemm_bf16x2<<<dim3(DIM_/GBN, BT_/GBM), 256>>>(x, Wq, q, BT_, DIM_, DIM_);
    gemm_bf16x2<<<dim3(KVD_/GBN, BT_/GBM), 256>>>(x, Wk, k, BT_, KVD_, DIM_);
    gemm_bf16x2<<<dim3(KVD_/GBN, BT_/GBM), 256>>>(x, Wv, v, BT_, KVD_, DIM_);

    // RMSNorm + RoPE + split (q gets the 1/8 attention scale folded in)
    rms_rope_split<<<(BT_*NH_*32)/256,  256>>>(q, qhp, qlp, NH_,  BT_*NH_,  0.125f);
    rms_rope_split<<<(BT_*NKV_*32)/256, 256>>>(k, khp, klp, NKV_, BT_*NKV_, 1.0f);
    split_v<<<(BT_*KVD_/4 + 255)/256, 256>>>(v, vhp, vlp, BT_*KVD_/4);

    // Tensor-core causal flash attention
    flash_tc<<<dim3(T_/64, NH_, B_), 128>>>(qhp, qlp, khp, klp, vhp, vlp, y);

    // Output projection
    gemm_bf16x2<<<dim3(DIM_/GBN, BT_/GBM), 256>>>(y, Wp, out, BT_, DIM_, DIM_);
}